// round 17
// baseline (speedup 1.0000x reference)
#include <cuda_runtime.h>
#include <math.h>

#define IMG_H 1088
#define IMG_W 1920
#define BATCH 8
#define TW 64      // tile width
#define TH 32      // tile height
#define NT 512

#define WI 80   // s_img stride; 80 cols loaded: [bx-8, bx+72)
#define WT 72   // s_tmp stride
#define WB 72   // s_blur stride (70 used)
#define WM 72   // s_mag/gx/gy stride (68 used; mult of 4 for float4 rows)
#define WN 68   // s_thin stride (66 used; mult of 4)

// Lifetime-packed dynamic smem layout (floats):
//   img [0,3520)  tmp [3520,6688)            (dead after stage 1b)
//   gx  [0,2592)  gy [2592,5184)  mag [5184,7776)   (overlay img/tmp)
//   thin[7776,10088)  blur [10088,12824)
// Max live = 12824 floats = 51296 B -> 3 CTAs/SM @ 512 thr = 48 warps.
#define OFF_IMG  0
#define OFF_TMP  3520
#define OFF_GX   0
#define OFF_GY   2592
#define OFF_MAG  5184
#define OFF_THIN 7776
#define OFF_BLUR 10088
#define SM_FLOATS 12824
#define SM_BYTES (SM_FLOATS * 4)

// cephes-style atan2, max err ~1e-7 rad
__device__ __forceinline__ float fast_atan2(float y, float x) {
    float ax = fabsf(x), ay = fabsf(y);
    float mx = fmaxf(ax, ay), mn = fminf(ax, ay);
    float t = __fdividef(mn, mx);
    if (mx == 0.0f) t = 0.0f;
    bool red = t > 0.4142135624f;
    float tr = __fdividef(t - 1.0f, t + 1.0f);
    float u = red ? tr : t;
    float z = u * u;
    float p = ((8.05374449538e-2f * z - 1.38776856032e-1f) * z
               + 1.99777106478e-1f) * z - 3.33329491539e-1f;
    float a = fmaf(p * z, u, u);
    if (red) a += 0.7853981634f;
    if (ay > ax) a = 1.5707963268f - a;
    if (x < 0.0f) a = 3.1415926536f - a;
    return (y < 0.0f) ? -a : a;
}

__global__ __launch_bounds__(NT, 3) void canny_kernel(
    const float* __restrict__ img,
    const float* __restrict__ gk,
    float* __restrict__ out,
    long long N)
{
    extern __shared__ __align__(16) float sbuf[];
    __shared__ float s_r[7], s_c[7];
    float* s_img  = sbuf + OFF_IMG;
    float* s_blur = sbuf + OFF_BLUR;
    float* s_mag  = sbuf + OFF_MAG;
    float* s_thin = sbuf + OFF_THIN;
    float* s_gx   = sbuf + OFF_GX;   // overlays dead img
    float* s_gy   = sbuf + OFF_GY;   // overlays dead img/tmp

    const int tid = threadIdx.x;
    const int bx = blockIdx.x * TW;
    const int by = blockIdx.y * TH;
    const int b  = blockIdx.z;
    const float* ip = img + (long long)b * (IMG_H * IMG_W);

    if (tid < 7) {
        // gaussian is a normalized outer product: k[i][j] = k[i][4]*k[4][j]/k[4][4]
        float s = sqrtf(gk[4 * 7 + 4]);
        s_r[tid] = gk[tid * 7 + 4] / s;   // vertical factor
        s_c[tid] = gk[4 * 7 + tid] / s;   // horizontal factor
    }

    // ---- stage 0: load img cols [bx-8, bx+72) (80 cols) x rows [by-6, by+38) ----
    if (bx >= 8 && bx + 72 <= IMG_W) {
        float4* img4 = (float4*)s_img;
        for (int idx = tid; idx < 44 * 20; idx += NT) {
            int r = idx / 20, v = idx - r * 20;
            int gy = by - 6 + r;
            float4 val = make_float4(0.f, 0.f, 0.f, 0.f);
            if ((unsigned)gy < IMG_H)
                val = *(const float4*)(ip + (long long)gy * IMG_W + (bx - 8) + 4 * v);
            img4[r * (WI / 4) + v] = val;
        }
    } else {
        for (int idx = tid; idx < 44 * 80; idx += NT) {
            int r = idx / 80, c = idx - r * 80;
            int gy = by - 6 + r, gx = bx - 8 + c;
            float v = 0.0f;
            if ((unsigned)gy < IMG_H && (unsigned)gx < IMG_W)
                v = ip[(long long)gy * IMG_W + gx];
            s_img[r * WI + c] = v;
        }
    }
    __syncthreads();

    const float c0 = s_c[0], c1 = s_c[1], c2 = s_c[2], c3 = s_c[3],
                c4 = s_c[4], c5 = s_c[5], c6 = s_c[6];
    const float r0 = s_r[0], r1 = s_r[1], r2 = s_r[2], r3 = s_r[3],
                r4 = s_r[4], r5 = s_r[5], r6 = s_r[6];

    // ---- stage 1a: horizontal 7-tap, float4-quad: 44 rows x 18 quads ----
    // tmp cols 4q..4q+3 need img locals 4q+2..4q+11 c [4q, 4q+12) = 3 float4s
    {
        const float4* img4 = (const float4*)s_img;
        float4* tmp4 = (float4*)(sbuf + OFF_TMP);
        for (int idx = tid; idx < 44 * 18; idx += NT) {
            int r = idx / 18, q = idx - r * 18;
            const float4* row = img4 + r * (WI / 4) + q;
            float4 A = row[0], B = row[1], C = row[2];
            float o0 = c0*A.z + c1*A.w + c2*B.x + c3*B.y + c4*B.z + c5*B.w + c6*C.x;
            float o1 = c0*A.w + c1*B.x + c2*B.y + c3*B.z + c4*B.w + c5*C.x + c6*C.y;
            float o2 = c0*B.x + c1*B.y + c2*B.z + c3*B.w + c4*C.x + c5*C.y + c6*C.z;
            float o3 = c0*B.y + c1*B.z + c2*B.w + c3*C.x + c4*C.y + c5*C.z + c6*C.w;
            tmp4[r * (WT / 4) + q] = make_float4(o0, o1, o2, o3);
        }
    }
    __syncthreads();

    // ---- stage 1b: vertical 7-tap -> blur 38x70; 35 pairs x 10 row-blocks ----
    {
        const float2* tmp2 = (const float2*)(sbuf + OFF_TMP);
        float2* blur2 = (float2*)s_blur;
        for (int idx = tid; idx < 35 * 10; idx += NT) {
            int p = idx % 35, rb = idx / 35;
            int rr = rb * 4;
            float2 tv[10];
            #pragma unroll
            for (int i = 0; i < 10; i++)
                tv[i] = (rr + i < 44) ? tmp2[(rr + i) * (WT / 2) + p]
                                      : make_float2(0.f, 0.f);
            int gx0 = bx - 3 + 2 * p;
            bool cok0 = (unsigned)gx0 < IMG_W;
            bool cok1 = (unsigned)(gx0 + 1) < IMG_W;
            #pragma unroll
            for (int i = 0; i < 4; i++) {
                int r = rr + i;
                if (r < 38) {
                    float vx = r0*tv[i].x + r1*tv[i+1].x + r2*tv[i+2].x + r3*tv[i+3].x
                             + r4*tv[i+4].x + r5*tv[i+5].x + r6*tv[i+6].x;
                    float vy = r0*tv[i].y + r1*tv[i+1].y + r2*tv[i+2].y + r3*tv[i+3].y
                             + r4*tv[i+4].y + r5*tv[i+5].y + r6*tv[i+6].y;
                    int gy = by - 3 + r;
                    bool rok = (unsigned)gy < IMG_H;
                    float2 o;
                    o.x = (rok && cok0) ? vx : 0.0f;
                    o.y = (rok && cok1) ? vy : 0.0f;
                    blur2[r * (WB / 2) + p] = o;
                }
            }
        }
    }
    __syncthreads();

    // ---- stage 2: sobel -> mag (masked) + gx,gy cached; 34 pairs x 9 blocks ----
    {
        const float2* blur2 = (const float2*)s_blur;
        float2* mag2 = (float2*)s_mag;
        float2* gx2  = (float2*)s_gx;
        float2* gy2  = (float2*)s_gy;
        for (int idx = tid; idx < 34 * 9; idx += NT) {
            int p = idx % 34, rb = idx / 34;
            int rr = rb * 4;
            float P0[6], P1[6], Q0[6], Q1[6];
            #pragma unroll
            for (int i = 0; i < 6; i++) {
                float2 e = blur2[(rr + i) * (WB / 2) + p];
                float2 f = blur2[(rr + i) * (WB / 2) + p + 1];
                float a = e.x, bb = e.y, cc = f.x, d = f.y;
                P0[i] = a - cc;           P1[i] = bb - d;
                Q0[i] = a + 2.0f*bb + cc; Q1[i] = bb + 2.0f*cc + d;
            }
            int gxp0 = bx - 2 + 2 * p;
            bool cok0 = (unsigned)gxp0 < IMG_W;
            bool cok1 = (unsigned)(gxp0 + 1) < IMG_W;
            #pragma unroll
            for (int i = 0; i < 4; i++) {
                int r = rr + i;
                float gxa = P0[i] + 2.0f*P0[i+1] + P0[i+2];
                float gya = Q0[i] - Q0[i+2];
                float gxb = P1[i] + 2.0f*P1[i+1] + P1[i+2];
                float gyb = Q1[i] - Q1[i+2];
                float ma = sqrtf(gxa*gxa + gya*gya);
                float mb = sqrtf(gxb*gxb + gyb*gyb);
                int gy = by - 2 + r;
                bool rok = (unsigned)gy < IMG_H;
                float2 om;
                om.x = (rok && cok0) ? ma : 0.0f;
                om.y = (rok && cok1) ? mb : 0.0f;
                mag2[r * (WM / 2) + p] = om;
                gx2 [r * (WM / 2) + p] = make_float2(gxa, gxb);
                gy2 [r * (WM / 2) + p] = make_float2(gya, gyb);
            }
        }
    }
    __syncthreads();

    // ---- stage 3: non-max suppression -> thin; 33 pairs x 9 row-blocks ----
    {
        const float2* mag2 = (const float2*)s_mag;
        float2* thin2 = (float2*)s_thin;
        for (int idx = tid; idx < 33 * 9; idx += NT) {
            int p = idx % 33, rb = idx / 33;
            int rr = rb * 4;
            float P0[6], P1[6], Q0[6], Q1[6], MB[6], MC[6];
            #pragma unroll
            for (int i = 0; i < 6; i++) {
                float2 e = make_float2(0.f, 0.f), f = make_float2(0.f, 0.f);
                if (rr + i < 36) {
                    e = mag2[(rr + i) * (WM / 2) + p];
                    f = mag2[(rr + i) * (WM / 2) + p + 1];
                }
                float a = e.x, bb = e.y, cc = f.x, d = f.y;
                P0[i] = a - cc;           P1[i] = bb - d;
                Q0[i] = a + 2.0f*bb + cc; Q1[i] = bb + 2.0f*cc + d;
                MB[i] = bb; MC[i] = cc;
            }
            int gxp0 = bx - 1 + 2 * p;
            bool cok0 = (unsigned)gxp0 < IMG_W;
            bool cok1 = (unsigned)(gxp0 + 1) < IMG_W;
            #pragma unroll
            for (int i = 0; i < 4; i++) {
                int r = rr + i;
                if (r < 34) {
                    float sxa = P0[i] + 2.0f*P0[i+1] + P0[i+2];
                    float sya = Q0[i] - Q0[i+2];
                    float ma  = MB[i+1];
                    float va = (ma >= sxa && ma >= sya) ? ma : 0.0f;
                    float sxb = P1[i] + 2.0f*P1[i+1] + P1[i+2];
                    float syb = Q1[i] - Q1[i+2];
                    float mbv = MC[i+1];
                    float vb = (mbv >= sxb && mbv >= syb) ? mbv : 0.0f;
                    int gy = by - 1 + r;
                    bool rok = (unsigned)gy < IMG_H;
                    float2 o;
                    o.x = (rok && cok0) ? va : 0.0f;
                    o.y = (rok && cok1) ? vb : 0.0f;
                    thin2[r * (WN / 2) + p] = o;
                }
            }
        }
    }
    __syncthreads();

    // ---- stage 4: hysteresis + 5 plane writes; 4 cols x 1 row per thread ----
    {
        int q = tid & 15;         // quad in row (0..15)
        int r = tid >> 4;         // output row (0..31)
        int cb = 4 * q;           // output col base (0..60)

        // thin window rows r..r+2, cols cb..cb+5 (thin origin -1,-1)
        int cs[6];
        unsigned m1 = 0;
        float tcf[4];
        {
            const float4* T0 = (const float4*)(s_thin + r * WN + cb);
            const float4* T1 = (const float4*)(s_thin + (r + 1) * WN + cb);
            const float4* T2 = (const float4*)(s_thin + (r + 2) * WN + cb);
            float4 a0 = T0[0], a1 = T0[1];
            float4 b0 = T1[0], b1 = T1[1];
            float4 d0 = T2[0], d1 = T2[1];
            float rowA[6] = {a0.x, a0.y, a0.z, a0.w, a1.x, a1.y};
            float rowB[6] = {b0.x, b0.y, b0.z, b0.w, b1.x, b1.y};
            float rowC[6] = {d0.x, d0.y, d0.z, d0.w, d1.x, d1.y};
            #pragma unroll
            for (int k = 0; k < 6; k++) {
                int sA = rowA[k] > 3.0f;
                int sB = rowB[k] > 3.0f;
                int sC = rowC[k] > 3.0f;
                cs[k] = sA + sB + sC;
                m1 |= ((unsigned)sB) << k;
            }
            tcf[0] = rowB[1]; tcf[1] = rowB[2]; tcf[2] = rowB[3]; tcf[3] = rowB[4];
        }

        // blur row r+3, cols cb+3..cb+6 (blur origin -3,-3)
        const float4* B4 = (const float4*)(s_blur + (r + 3) * WB + cb);
        float4 bA = B4[0], bB = B4[1];
        float4 oB = make_float4(bA.w, bB.x, bB.y, bB.z);

        // mag/gx/gy row r+2, cols cb+2..cb+5 (origin -2,-2)
        const float4* M4 = (const float4*)(s_mag + (r + 2) * WM + cb);
        float4 mA = M4[0], mB = M4[1];
        float4 oM = make_float4(mA.z, mA.w, mB.x, mB.y);
        const float4* X4 = (const float4*)(s_gx + (r + 2) * WM + cb);
        float4 xA = X4[0], xB = X4[1];
        const float4* Y4 = (const float4*)(s_gy + (r + 2) * WM + cb);
        float4 yA = Y4[0], yB = Y4[1];
        float gxv[4] = {xA.z, xA.w, xB.x, xB.y};
        float gyv[4] = {yA.z, yA.w, yB.x, yB.y};

        float4 oO, oT, oE;
        float* pO = (float*)&oO; float* pT = (float*)&oT; float* pE = (float*)&oE;
        #pragma unroll
        for (int j = 0; j < 4; j++) {
            float tc = tcf[j];
            bool strong = tc > 3.0f;
            bool weak   = (tc > 1.0f) && (tc <= 3.0f);
            int full9 = cs[j] + cs[j + 1] + cs[j + 2];
            int centerStrong = (m1 >> (j + 1)) & 1;
            // conv with hyst_k (center -8) > 0  <=>  full9 - 9*center_strong > 0
            bool sn   = (full9 - 9 * centerStrong) > 0;
            bool edge = strong || (weak && sn);
            pO[j] = fast_atan2(gyv[j], gxv[j]);
            pT[j] = tc;
            pE[j] = edge ? 1.0f : 0.0f;
        }

        long long o = (long long)b * (IMG_H * IMG_W)
                    + (long long)(by + r) * IMG_W + (bx + cb);
        *(float4*)(out + o)         = oB;
        *(float4*)(out + N + o)     = oM;
        *(float4*)(out + 2 * N + o) = oO;
        *(float4*)(out + 3 * N + o) = oT;
        *(float4*)(out + 4 * N + o) = oE;
    }
}

extern "C" void kernel_launch(void* const* d_in, const int* in_sizes, int n_in,
                              void* d_out, int out_size) {
    const float* img = (const float*)d_in[0];
    const float* gk  = (const float*)d_in[1];
    float* out = (float*)d_out;
    long long N = (long long)out_size / 5;   // 5 concatenated planes
    // opt-in to >48KB dynamic smem (idempotent host call, not an allocation)
    cudaFuncSetAttribute(canny_kernel,
                         cudaFuncAttributeMaxDynamicSharedMemorySize, SM_BYTES);
    dim3 grid(IMG_W / TW, IMG_H / TH, BATCH);
    canny_kernel<<<grid, NT, SM_BYTES>>>(img, gk, out, N);
}